// round 3
// baseline (speedup 1.0000x reference)
#include <cuda_runtime.h>

typedef unsigned long long u64;

// Problem constants
constexpr int Bb = 8;
constexpr int Ss = 8192;
constexpr int Dd = 128;
constexpr int N3 = 384;                 // 3 * H * hd
constexpr int ROWS = Bb * Ss;           // 65536
constexpr int RPI = 8;                  // rows per iteration (kernel 1)
constexpr int ITERS = ROWS / RPI;       // 8192
constexpr int K1_GRID = 444;            // 3 waves at 1 CTA/SM on 148 SMs
constexpr int K1_THREADS = 384;

// Final GEMM: (1024 x 8192) @ (8192 x 128)
constexpr int M2 = Bb * Dd;             // 1024
constexpr int K2 = Ss;                  // 8192
constexpr int N2 = Dd;                  // 128
constexpr int TILE_M = 64;
constexpr int KSPLIT = 16;
constexpr int KCHUNK = K2 / KSPLIT;     // 512
constexpr int KT = 32;
constexpr int K2_THREADS = 256;

// Scratch (device globals; no runtime allocation)
__device__ __align__(256) float g_A[ROWS * Dd];            // attention output, 33.5 MB
__device__ __align__(256) float g_part[KSPLIT * M2 * N2];  // split-K partials, 8 MB

// ---- packed f32x2 helpers (B300: FFMA2 restores full-rate fp32) ----
__device__ __forceinline__ u64 pack2(float lo, float hi) {
    u64 r; asm("mov.b64 %0, {%1, %2};" : "=l"(r) : "f"(lo), "f"(hi)); return r;
}
__device__ __forceinline__ void unpack2(u64 v, float& lo, float& hi) {
    asm("mov.b64 {%0, %1}, %2;" : "=f"(lo), "=f"(hi) : "l"(v));
}
__device__ __forceinline__ u64 ffma2(u64 a, u64 b, u64 c) {
    u64 d; asm("fma.rn.f32x2 %0, %1, %2, %3;" : "=l"(d) : "l"(a), "l"(b), "l"(c)); return d;
}

// ============================================================================
// Kernel 1: fused QKV projection + per-position 4x4 head-mixing attention
//   thread j (0..383) owns QKV column j; W_qkv column held in 128 registers.
//   8 rows per iteration, packed as 4 f32x2 row-pairs.
// ============================================================================
__global__ __launch_bounds__(K1_THREADS, 1)
void qkv_attn_kernel(const float* __restrict__ x,
                     const float* __restrict__ Wqkv,
                     const float* __restrict__ bqkv)
{
    __shared__ __align__(16) float xs[4 * 128 * 2];  // [pair][k] as interleaved float2
    __shared__ float qs[RPI][N3];                    // qkv rows
    __shared__ float sc[RPI][16];                    // raw scores
    __shared__ float pr[RPI][16];                    // softmax probs

    const int tid = threadIdx.x;

    // W_qkv column j -> registers (reused across all row iterations of this CTA)
    float Wc[128];
    #pragma unroll
    for (int k = 0; k < 128; ++k) Wc[k] = Wqkv[k * N3 + tid];
    const float bj = bqkv[tid];

    for (int it = blockIdx.x; it < ITERS; it += gridDim.x) {
        const int row0 = it * RPI;

        __syncthreads();  // protect xs/qs/pr from previous iteration's readers
        for (int i = tid; i < RPI * 128; i += K1_THREADS) {
            const int r = i >> 7, k = i & 127;
            // interleave rows (2p, 2p+1) into the two lanes of an f32x2
            xs[((r >> 1) * 128 + k) * 2 + (r & 1)] =
                x[(long long)(row0 + r) * 128 + k];
        }
        __syncthreads();

        // ---- QKV GEMM: 8 rows x column j, K=128 ----
        u64 acc0 = pack2(bj, bj), acc1 = acc0, acc2 = acc0, acc3 = acc0;
        const u64* xs2 = reinterpret_cast<const u64*>(xs);
        #pragma unroll
        for (int k = 0; k < 128; ++k) {
            const u64 w2 = pack2(Wc[k], Wc[k]);
            acc0 = ffma2(xs2[0 * 128 + k], w2, acc0);
            acc1 = ffma2(xs2[1 * 128 + k], w2, acc1);
            acc2 = ffma2(xs2[2 * 128 + k], w2, acc2);
            acc3 = ffma2(xs2[3 * 128 + k], w2, acc3);
        }
        {
            float lo, hi;
            unpack2(acc0, lo, hi); qs[0][tid] = lo; qs[1][tid] = hi;
            unpack2(acc1, lo, hi); qs[2][tid] = lo; qs[3][tid] = hi;
            unpack2(acc2, lo, hi); qs[4][tid] = lo; qs[5][tid] = hi;
            unpack2(acc3, lo, hi); qs[6][tid] = lo; qs[7][tid] = hi;
        }
        __syncthreads();

        // ---- scores: per row, 4x4 = 16 dots of length 32 (128 threads) ----
        if (tid < 128) {
            const int r = tid >> 4, qi = (tid >> 2) & 3, ki = tid & 3;
            const float* q  = &qs[r][qi * 96];        // q  = qkv[h][0:32]
            const float* kk = &qs[r][ki * 96 + 32];   // k  = qkv[h][32:64]
            float s = 0.f;
            #pragma unroll
            for (int d = 0; d < 32; ++d) s = fmaf(q[d], kk[d], s);
            sc[r][qi * 4 + ki] = s * 0.17677669529663687f;  // 1/sqrt(32)
        }
        __syncthreads();

        // ---- softmax over ki (32 threads) ----
        if (tid < 32) {
            const int r = tid >> 2, qi = tid & 3;
            const float a = sc[r][qi * 4 + 0], b = sc[r][qi * 4 + 1];
            const float c = sc[r][qi * 4 + 2], d = sc[r][qi * 4 + 3];
            const float m = fmaxf(fmaxf(a, b), fmaxf(c, d));
            const float ea = expf(a - m), eb = expf(b - m);
            const float ec = expf(c - m), ed = expf(d - m);
            const float inv = 1.f / (ea + eb + ec + ed);
            pr[r][qi * 4 + 0] = ea * inv; pr[r][qi * 4 + 1] = eb * inv;
            pr[r][qi * 4 + 2] = ec * inv; pr[r][qi * 4 + 3] = ed * inv;
        }
        __syncthreads();

        // ---- out[qi][d] = sum_ki attn[qi][ki] * v[ki][d];  v = qkv[h][64:96] ----
        for (int i = tid; i < RPI * 128; i += K1_THREADS) {
            const int r = i >> 7, c = i & 127, h = c >> 5, d = c & 31;
            const float o = pr[r][h * 4 + 0] * qs[r][0 * 96 + 64 + d]
                          + pr[r][h * 4 + 1] * qs[r][1 * 96 + 64 + d]
                          + pr[r][h * 4 + 2] * qs[r][2 * 96 + 64 + d]
                          + pr[r][h * 4 + 3] * qs[r][3 * 96 + 64 + d];
            g_A[(long long)(row0 + r) * 128 + c] = o;
        }
    }
}

// ============================================================================
// Kernel 2: split-K GEMM  (1024 x 8192) @ W_out(8192 x 128) -> partials
//   grid (16 row-tiles, 16 K-splits); 256 threads; 4x8 micro-tile per thread
//   (8 cols packed as 4 f32x2 accumulator pairs).
// ============================================================================
__global__ __launch_bounds__(K2_THREADS)
void gemm2_kernel(const float* __restrict__ Wout)
{
    __shared__ __align__(16) float As[TILE_M][KT + 4];  // 64 x 36 (padded)
    __shared__ __align__(16) float Ws[KT][N2];          // 32 x 128

    const int tid = threadIdx.x;
    const int tx = tid & 15;        // cols tx*8 .. tx*8+7
    const int ty = tid >> 4;        // rows ty*4 .. ty*4+3
    const int m0 = blockIdx.x * TILE_M;
    const int k0 = blockIdx.y * KCHUNK;

    u64 acc[4][4];
    #pragma unroll
    for (int r = 0; r < 4; ++r)
        #pragma unroll
        for (int c = 0; c < 4; ++c) acc[r][c] = 0ULL;  // (+0.f, +0.f)

    for (int kt = 0; kt < KCHUNK; kt += KT) {
        __syncthreads();
        // A tile: 64 x 32  (float4 loads)
        #pragma unroll
        for (int i = tid; i < 512; i += K2_THREADS) {
            const int row = i >> 3, kq = i & 7;
            const float4 v = *reinterpret_cast<const float4*>(
                &g_A[(long long)(m0 + row) * K2 + k0 + kt + kq * 4]);
            *reinterpret_cast<float4*>(&As[row][kq * 4]) = v;
        }
        // W tile: 32 x 128  (float4 loads)
        #pragma unroll
        for (int i = tid; i < 1024; i += K2_THREADS) {
            const int kk = i >> 5, cq = i & 31;
            const float4 v = *reinterpret_cast<const float4*>(
                &Wout[(long long)(k0 + kt + kk) * N2 + cq * 4]);
            *reinterpret_cast<float4*>(&Ws[kk][cq * 4]) = v;
        }
        __syncthreads();

        #pragma unroll
        for (int k = 0; k < KT; ++k) {
            u64 bv[4];
            const u64* wrow = reinterpret_cast<const u64*>(&Ws[k][0]);
            #pragma unroll
            for (int c = 0; c < 4; ++c) bv[c] = wrow[tx * 4 + c];
            #pragma unroll
            for (int r = 0; r < 4; ++r) {
                const float a = As[ty * 4 + r][k];
                const u64 a2 = pack2(a, a);
                #pragma unroll
                for (int c = 0; c < 4; ++c) acc[r][c] = ffma2(a2, bv[c], acc[r][c]);
            }
        }
    }

    float* dst = &g_part[(long long)blockIdx.y * M2 * N2];
    #pragma unroll
    for (int r = 0; r < 4; ++r) {
        const int m = m0 + ty * 4 + r;
        #pragma unroll
        for (int c = 0; c < 4; ++c) {
            float lo, hi; unpack2(acc[r][c], lo, hi);
            dst[(long long)m * N2 + tx * 8 + c * 2 + 0] = lo;
            dst[(long long)m * N2 + tx * 8 + c * 2 + 1] = hi;
        }
    }
}

// ============================================================================
// Kernel 3: reduce split-K partials + bias -> output (8,128,128)
// ============================================================================
__global__ void reduce_kernel(float* __restrict__ out, const float* __restrict__ bout)
{
    const int i = blockIdx.x * blockDim.x + threadIdx.x;  // < 131072
    float s = bout[i & 127];
    #pragma unroll
    for (int ks = 0; ks < KSPLIT; ++ks) s += g_part[ks * M2 * N2 + i];
    out[i] = s;
}

extern "C" void kernel_launch(void* const* d_in, const int* in_sizes, int n_in,
                              void* d_out, int out_size)
{
    (void)in_sizes; (void)n_in; (void)out_size;
    const float* x    = (const float*)d_in[0];
    const float* Wqkv = (const float*)d_in[1];
    const float* bqkv = (const float*)d_in[2];
    const float* Wout = (const float*)d_in[3];
    const float* bout = (const float*)d_in[4];
    float* out = (float*)d_out;

    qkv_attn_kernel<<<K1_GRID, K1_THREADS>>>(x, Wqkv, bqkv);
    dim3 g2(M2 / TILE_M, KSPLIT);
    gemm2_kernel<<<g2, K2_THREADS>>>(Wout);
    reduce_kernel<<<(M2 * N2) / 256, 256>>>(out, bout);
}

// round 4
// speedup vs baseline: 1.0904x; 1.0904x over previous
#include <cuda_runtime.h>

typedef unsigned long long u64;

// Problem constants
constexpr int Bb = 8;
constexpr int Ss = 8192;
constexpr int Dd = 128;
constexpr int N3 = 384;                 // 3 * H * hd
constexpr int ROWS = Bb * Ss;           // 65536

// Kernel 1 tiling
constexpr int RT = 64;                  // rows per CTA
constexpr int CT = 512;                 // threads per CTA
constexpr int KC = 32;                  // K-chunk staged in shared
constexpr int K1_GRID = ROWS / RT;      // 1024
constexpr int SMEM_POOL = RT * N3;      // 24576 floats = 96 KB (qs view)

// Final GEMM: (1024 x 8192) @ (8192 x 128)
constexpr int M2 = Bb * Dd;             // 1024
constexpr int K2 = Ss;                  // 8192
constexpr int N2 = Dd;                  // 128
constexpr int TILE_M = 64;
constexpr int KSPLIT = 16;
constexpr int KCHUNK = K2 / KSPLIT;     // 512
constexpr int KT = 32;
constexpr int K2_THREADS = 256;

// Scratch (device globals; no runtime allocation)
__device__ __align__(256) float g_A[ROWS * Dd];            // attention output, 33.5 MB
__device__ __align__(256) float g_part[KSPLIT * M2 * N2];  // split-K partials, 8 MB

// ---- packed f32x2 helpers ----
__device__ __forceinline__ u64 pack2(float lo, float hi) {
    u64 r; asm("mov.b64 %0, {%1, %2};" : "=l"(r) : "f"(lo), "f"(hi)); return r;
}
__device__ __forceinline__ void unpack2(u64 v, float& lo, float& hi) {
    asm("mov.b64 {%0, %1}, %2;" : "=f"(lo), "=f"(hi) : "l"(v));
}
__device__ __forceinline__ u64 ffma2(u64 a, u64 b, u64 c) {
    u64 d; asm("fma.rn.f32x2 %0, %1, %2, %3;" : "=l"(d) : "l"(a), "l"(b), "l"(c)); return d;
}

// ============================================================================
// Kernel 1: register-blocked QKV GEMM + fused per-position attention epilogue
//   CTA: 64 rows x 384 cols, K=128 (W staged in K-chunks of 32).
//   Thread micro-tile: 8 rows (4 f32x2 pairs) x 6 cols (cb + 64*j) ->
//   24 FFMA2 per 10 LDS per k: fma-pipe-bound.
// ============================================================================
__global__ __launch_bounds__(CT, 1)
void qkv_attn_kernel(const float* __restrict__ x,
                     const float* __restrict__ Wqkv,
                     const float* __restrict__ bqkv)
{
    extern __shared__ float pool[];            // 24576 floats (96 KB)
    float* xs = pool;                          // [32 pairs][128 k][2 lanes] = 8192 floats
    float* Ws = pool + 8192;                   // [KC][384] = 12288 floats
    float* qs = pool;                          // epilogue view [64][384] (reuses pool)
    __shared__ float sc[RT][16];
    __shared__ float pr[RT][16];

    const int tid = threadIdx.x;
    const int rb  = tid >> 6;                  // row block 0..7 (rows rb*8..rb*8+7)
    const int cb  = tid & 63;                  // col lane: cols cb + 64*j
    const long long row0 = (long long)blockIdx.x * RT;

    // ---- stage x tile (64x128) into xs, row-pair interleaved ----
    for (int i = tid; i < RT * 128; i += CT) {
        const int r = i >> 7, k = i & 127;
        xs[((r >> 1) * 128 + k) * 2 + (r & 1)] = x[(row0 + r) * 128 + k];
    }

    // ---- accumulators init with bias ----
    u64 acc[4][6];
    #pragma unroll
    for (int j = 0; j < 6; ++j) {
        const float b = bqkv[cb + 64 * j];
        const u64 b2 = pack2(b, b);
        #pragma unroll
        for (int p = 0; p < 4; ++p) acc[p][j] = b2;
    }

    // ---- GEMM mainloop over K in chunks of KC ----
    const u64* xs2 = reinterpret_cast<const u64*>(xs);
    for (int kc = 0; kc < 128; kc += KC) {
        __syncthreads();   // xs ready (first iter) / previous chunk consumed
        for (int i = tid * 4; i < KC * N3; i += CT * 4) {
            *reinterpret_cast<float4*>(&Ws[i]) =
                *reinterpret_cast<const float4*>(&Wqkv[kc * N3 + i]);
        }
        __syncthreads();

        #pragma unroll 4
        for (int k = 0; k < KC; ++k) {
            u64 xv[4];
            #pragma unroll
            for (int p = 0; p < 4; ++p)
                xv[p] = xs2[(rb * 4 + p) * 128 + kc + k];   // broadcast LDS.64
            #pragma unroll
            for (int j = 0; j < 6; ++j) {
                const float w = Ws[k * N3 + cb + 64 * j];    // conflict-free LDS.32
                const u64 w2 = pack2(w, w);
                #pragma unroll
                for (int p = 0; p < 4; ++p) acc[p][j] = ffma2(xv[p], w2, acc[p][j]);
            }
        }
    }

    // ---- spill C tile to shared (pool reused as qs[64][384]) ----
    __syncthreads();
    #pragma unroll
    for (int p = 0; p < 4; ++p) {
        const int r = rb * 8 + 2 * p;
        #pragma unroll
        for (int j = 0; j < 6; ++j) {
            float lo, hi; unpack2(acc[p][j], lo, hi);
            qs[r * N3 + cb + 64 * j]       = lo;
            qs[(r + 1) * N3 + cb + 64 * j] = hi;
        }
    }
    __syncthreads();

    // ---- scores: 64 rows x 4x4 head-mixing, dots of length 32 ----
    #pragma unroll
    for (int s = 0; s < 2; ++s) {
        const int id = tid * 2 + s;            // 0..1023
        const int r = id >> 4, qi = (id >> 2) & 3, ki = id & 3;
        const float* q  = &qs[r * N3 + qi * 96];        // q  = qkv[h][0:32]
        const float* kk = &qs[r * N3 + ki * 96 + 32];   // k  = qkv[h][32:64]
        float sum = 0.f;
        #pragma unroll
        for (int d = 0; d < 32; ++d) sum = fmaf(q[d], kk[d], sum);
        sc[r][qi * 4 + ki] = sum * 0.17677669529663687f;  // 1/sqrt(32)
    }
    __syncthreads();

    // ---- softmax over ki ----
    if (tid < 256) {
        const int r = tid >> 2, qi = tid & 3;
        const float a = sc[r][qi * 4 + 0], b = sc[r][qi * 4 + 1];
        const float c = sc[r][qi * 4 + 2], d = sc[r][qi * 4 + 3];
        const float m = fmaxf(fmaxf(a, b), fmaxf(c, d));
        const float ea = expf(a - m), eb = expf(b - m);
        const float ec = expf(c - m), ed = expf(d - m);
        const float inv = 1.f / (ea + eb + ec + ed);
        pr[r][qi * 4 + 0] = ea * inv; pr[r][qi * 4 + 1] = eb * inv;
        pr[r][qi * 4 + 2] = ec * inv; pr[r][qi * 4 + 3] = ed * inv;
    }
    __syncthreads();

    // ---- out[r][h*32+d] = sum_ki pr[r][h,ki] * v[ki][d];  v = qkv[h][64:96] ----
    #pragma unroll
    for (int s = 0; s < 16; ++s) {
        const int i = s * CT + tid;            // 0..8191
        const int r = i >> 7, c = i & 127, h = c >> 5, d = c & 31;
        const float o = pr[r][h * 4 + 0] * qs[r * N3 + 0 * 96 + 64 + d]
                      + pr[r][h * 4 + 1] * qs[r * N3 + 1 * 96 + 64 + d]
                      + pr[r][h * 4 + 2] * qs[r * N3 + 2 * 96 + 64 + d]
                      + pr[r][h * 4 + 3] * qs[r * N3 + 3 * 96 + 64 + d];
        g_A[(row0 + r) * 128 + c] = o;
    }
}

// ============================================================================
// Kernel 2: split-K GEMM  (1024 x 8192) @ W_out(8192 x 128) -> partials
// ============================================================================
__global__ __launch_bounds__(K2_THREADS)
void gemm2_kernel(const float* __restrict__ Wout)
{
    __shared__ __align__(16) float As[TILE_M][KT + 4];  // 64 x 36 (padded)
    __shared__ __align__(16) float Wsh[KT][N2];         // 32 x 128

    const int tid = threadIdx.x;
    const int tx = tid & 15;        // cols tx*8 .. tx*8+7
    const int ty = tid >> 4;        // rows ty*4 .. ty*4+3
    const int m0 = blockIdx.x * TILE_M;
    const int k0 = blockIdx.y * KCHUNK;

    u64 acc[4][4];
    #pragma unroll
    for (int r = 0; r < 4; ++r)
        #pragma unroll
        for (int c = 0; c < 4; ++c) acc[r][c] = 0ULL;

    for (int kt = 0; kt < KCHUNK; kt += KT) {
        __syncthreads();
        #pragma unroll
        for (int i = tid; i < 512; i += K2_THREADS) {
            const int row = i >> 3, kq = i & 7;
            const float4 v = *reinterpret_cast<const float4*>(
                &g_A[(long long)(m0 + row) * K2 + k0 + kt + kq * 4]);
            *reinterpret_cast<float4*>(&As[row][kq * 4]) = v;
        }
        #pragma unroll
        for (int i = tid; i < 1024; i += K2_THREADS) {
            const int kk = i >> 5, cq = i & 31;
            const float4 v = *reinterpret_cast<const float4*>(
                &Wout[(long long)(k0 + kt + kk) * N2 + cq * 4]);
            *reinterpret_cast<float4*>(&Wsh[kk][cq * 4]) = v;
        }
        __syncthreads();

        #pragma unroll
        for (int k = 0; k < KT; ++k) {
            u64 bv[4];
            const u64* wrow = reinterpret_cast<const u64*>(&Wsh[k][0]);
            #pragma unroll
            for (int c = 0; c < 4; ++c) bv[c] = wrow[tx * 4 + c];
            #pragma unroll
            for (int r = 0; r < 4; ++r) {
                const float a = As[ty * 4 + r][k];
                const u64 a2 = pack2(a, a);
                #pragma unroll
                for (int c = 0; c < 4; ++c) acc[r][c] = ffma2(a2, bv[c], acc[r][c]);
            }
        }
    }

    float* dst = &g_part[(long long)blockIdx.y * M2 * N2];
    #pragma unroll
    for (int r = 0; r < 4; ++r) {
        const int m = m0 + ty * 4 + r;
        #pragma unroll
        for (int c = 0; c < 4; ++c) {
            float lo, hi; unpack2(acc[r][c], lo, hi);
            dst[(long long)m * N2 + tx * 8 + c * 2 + 0] = lo;
            dst[(long long)m * N2 + tx * 8 + c * 2 + 1] = hi;
        }
    }
}

// ============================================================================
// Kernel 3: reduce split-K partials + bias -> output (8,128,128)
// ============================================================================
__global__ void reduce_kernel(float* __restrict__ out, const float* __restrict__ bout)
{
    const int i = blockIdx.x * blockDim.x + threadIdx.x;  // < 131072
    float s = bout[i & 127];
    #pragma unroll
    for (int ks = 0; ks < KSPLIT; ++ks) s += g_part[ks * M2 * N2 + i];
    out[i] = s;
}

extern "C" void kernel_launch(void* const* d_in, const int* in_sizes, int n_in,
                              void* d_out, int out_size)
{
    (void)in_sizes; (void)n_in; (void)out_size;
    const float* x    = (const float*)d_in[0];
    const float* Wqkv = (const float*)d_in[1];
    const float* bqkv = (const float*)d_in[2];
    const float* Wout = (const float*)d_in[3];
    const float* bout = (const float*)d_in[4];
    float* out = (float*)d_out;

    static int smem_set = 0;
    if (!smem_set) {
        cudaFuncSetAttribute(qkv_attn_kernel,
                             cudaFuncAttributeMaxDynamicSharedMemorySize,
                             SMEM_POOL * (int)sizeof(float));
        smem_set = 1;
    }

    qkv_attn_kernel<<<K1_GRID, CT, SMEM_POOL * sizeof(float)>>>(x, Wqkv, bqkv);
    dim3 g2(M2 / TILE_M, KSPLIT);
    gemm2_kernel<<<g2, K2_THREADS>>>(Wout);
    reduce_kernel<<<(M2 * N2) / 256, 256>>>(out, bout);
}